// round 4
// baseline (speedup 1.0000x reference)
#include <cuda_runtime.h>
#include <cstdint>
#include <cstddef>

// ============================================================================
// ComplexMixture on GB300 via legacy mma.sync (PTX target is compute_103 —
// tcgen05/TMA are unavailable; sm_80-class mma.sync IS available).
//
// out_real = (R^T R + I^T I)/S ; out_imag = (R^T I - (R^T I)^T)/S
// Per batch: G = X^T X, X = [R | I] (S x 128). G is symmetric -> compute only
// the 10 upper 32x32 warp tiles out of 16. K split across 4 CTAs per batch,
// partials to scratch, deterministic combine kernel.
// ============================================================================

namespace {
constexpr int kB = 32;
constexpr int kS = 8192;
constexpr int kD = 64;
constexpr int kM = 128;                  // 2*D
constexpr int kSplit = 4;
constexpr int kBK = 32;                  // K per pipeline stage
constexpr int kKper = kS / kSplit;       // 2048
constexpr int kIters = kKper / kBK;      // 64
constexpr int kPad = 36;                 // Xt row stride in floats (bank magic)
}  // namespace

// Partial Gram scratch: [B][SPLIT][128][128] f32 = 8 MB (upper tiles valid)
__device__ float g_scratch[(size_t)kB * kSplit * kM * kM];

__device__ __forceinline__ float tf32_rn(float x) {
    uint32_t v;
    asm("cvt.rna.tf32.f32 %0, %1;" : "=r"(v) : "f"(x));
    return __uint_as_float(v);
}

__device__ __forceinline__ void mma_tf32(float* d, const float* a, const float* b) {
    asm volatile(
        "mma.sync.aligned.m16n8k8.row.col.f32.tf32.tf32.f32 "
        "{%0,%1,%2,%3}, {%4,%5,%6,%7}, {%8,%9}, {%0,%1,%2,%3};"
        : "+f"(d[0]), "+f"(d[1]), "+f"(d[2]), "+f"(d[3])
        : "r"(__float_as_uint(a[0])), "r"(__float_as_uint(a[1])),
          "r"(__float_as_uint(a[2])), "r"(__float_as_uint(a[3])),
          "r"(__float_as_uint(b[0])), "r"(__float_as_uint(b[1])));
}

// ---------------------------------------------------------------------------
// Kernel 1: per-(batch, split) partial Gram via mma.sync tf32.
// 320 threads = 10 warps; warp w owns upper 32x32 tile (ti, tj).
// Threads 0..255 are also the loaders.
// ---------------------------------------------------------------------------
__global__ void __launch_bounds__(320, 1)
gram_kernel(const float* __restrict__ xr, const float* __restrict__ xi) {
    __shared__ float xt[2][kM][kPad];  // 36864 B

    const int t = threadIdx.x;
    const int wid = t >> 5;
    const int lane = t & 31;
    const int b = blockIdx.x >> 2;
    const int p = blockIdx.x & 3;

    // Upper-triangle 32x32 tile assignment for the 10 warps.
    const int ti_tab[10] = {0, 0, 0, 0, 1, 1, 1, 2, 2, 3};
    const int tj_tab[10] = {0, 1, 2, 3, 1, 2, 3, 2, 3, 3};
    const int ti = ti_tab[wid];
    const int tj = tj_tab[wid];

    float acc[2][4][4];
#pragma unroll
    for (int mt = 0; mt < 2; ++mt)
#pragma unroll
        for (int nt = 0; nt < 4; ++nt)
#pragma unroll
            for (int e = 0; e < 4; ++e) acc[mt][nt][e] = 0.0f;

    // Loader mapping: lane -> (kq = lane&3, mr = lane>>2); k_in = 4*wid + kq.
    // LDG: per instr a warp reads 4 contiguous rows x 32B chunks (full sectors)
    // STS bank = (4*(mr+8j) + k_in) mod 32 = (4*mr + k_in + 4*wid) mod 32 ->
    //            all 32 banks within a warp: conflict-free.
    const int kq = lane & 3;
    const int mr = lane >> 2;
    const int k_in = (wid & 7) * 4 + kq;
    const bool loader = (t < 256);

    const size_t base_off =
        ((size_t)b * kS + (size_t)p * kKper + (size_t)k_in) * kD + (size_t)mr;
    const float* pr = xr + base_off;
    const float* pi = xi + base_off;

    float cr[8], ci[8];
    if (loader) {
#pragma unroll
        for (int j = 0; j < 8; ++j) {
            cr[j] = pr[8 * j];
            ci[j] = pi[8 * j];
        }
    }

    const int fr = lane >> 2;  // fragment row-in-group
    const int fc = lane & 3;   // fragment col-in-group (k)

    for (int it = 0; it < kIters; ++it) {
        const int s = it & 1;

        __syncthreads();  // buf s free (its previous consumers finished)
        if (loader) {
#pragma unroll
            for (int j = 0; j < 8; ++j) {
                xt[s][mr + 8 * j][k_in] = tf32_rn(cr[j]);
                xt[s][64 + mr + 8 * j][k_in] = tf32_rn(ci[j]);
            }
        }
        __syncthreads();  // buf s ready

        // Prefetch next stage into registers (overlaps with MMA below).
        if (loader && it + 1 < kIters) {
            const float* prn = pr + (size_t)(it + 1) * kBK * kD;
            const float* pin = pi + (size_t)(it + 1) * kBK * kD;
#pragma unroll
            for (int j = 0; j < 8; ++j) {
                cr[j] = prn[8 * j];
                ci[j] = pin[8 * j];
            }
        }

        // MMA over the BK=32 stage: 4 k8 steps.
#pragma unroll
        for (int q = 0; q < 4; ++q) {
            const int kl = q * 8 + fc;
            float a[2][4];
#pragma unroll
            for (int mt = 0; mt < 2; ++mt) {
                const int r0 = ti * 32 + mt * 16;
                a[mt][0] = xt[s][r0 + fr][kl];
                a[mt][1] = xt[s][r0 + fr + 8][kl];
                a[mt][2] = xt[s][r0 + fr][kl + 4];
                a[mt][3] = xt[s][r0 + fr + 8][kl + 4];
            }
            float bf[4][2];
#pragma unroll
            for (int nt = 0; nt < 4; ++nt) {
                const int c0 = tj * 32 + nt * 8;
                bf[nt][0] = xt[s][c0 + fr][kl];
                bf[nt][1] = xt[s][c0 + fr][kl + 4];
            }
#pragma unroll
            for (int mt = 0; mt < 2; ++mt)
#pragma unroll
                for (int nt = 0; nt < 4; ++nt)
                    mma_tf32(acc[mt][nt], a[mt], bf[nt]);
        }
    }

    // Epilogue: write this warp's 32x32 tile to scratch (float2 stores).
    float* scr = g_scratch + (size_t)(b * kSplit + p) * kM * kM;
#pragma unroll
    for (int mt = 0; mt < 2; ++mt) {
#pragma unroll
        for (int nt = 0; nt < 4; ++nt) {
            const int row = ti * 32 + mt * 16 + fr;
            const int col = tj * 32 + nt * 8 + 2 * fc;
            float2 v0 = make_float2(acc[mt][nt][0], acc[mt][nt][1]);
            float2 v1 = make_float2(acc[mt][nt][2], acc[mt][nt][3]);
            *reinterpret_cast<float2*>(scr + (size_t)row * kM + col) = v0;
            *reinterpret_cast<float2*>(scr + (size_t)(row + 8) * kM + col) = v1;
        }
    }
}

// ---------------------------------------------------------------------------
// Kernel 2: deterministic combine of the 4 K-split partials with mirroring
// for the skipped lower-triangle tiles (G is symmetric).
// out_real[b][i][j] = sum_p (G(i,j) + G(64+i,64+j)) / S
// out_imag[b][i][j] = sum_p (G(i,64+j) - G(j,64+i)) / S   (both upper tiles)
// ---------------------------------------------------------------------------
__global__ void __launch_bounds__(256)
combine_kernel(float* __restrict__ out) {
    const int b = blockIdx.x;
    const float invS = 1.0f / (float)kS;
    float* out_r = out + (size_t)b * kD * kD;
    float* out_i = out + (size_t)kB * kD * kD + (size_t)b * kD * kD;
    const float* base = g_scratch + (size_t)b * kSplit * kM * kM;

    for (int idx = threadIdx.x; idx < kD * kD; idx += 256) {
        const int i = idx >> 6;
        const int j = idx & 63;
        const bool up = (j >> 5) >= (i >> 5);  // tile (i>>5, j>>5) computed?
        float ar = 0.0f, ai = 0.0f;
#pragma unroll
        for (int pp = 0; pp < kSplit; ++pp) {
            const float* G = base + (size_t)pp * kM * kM;
            // G(i,j) block (0,0) and G(64+i,64+j) block (1,1): mirror if needed
            ar += up ? (G[i * kM + j] + G[(64 + i) * kM + (64 + j)])
                     : (G[j * kM + i] + G[(64 + j) * kM + (64 + i)]);
            // Block (0,1) tiles are always upper (tj>=2>ti range) -> computed.
            ai += G[i * kM + (64 + j)] - G[j * kM + (64 + i)];
        }
        out_r[idx] = ar * invS;
        out_i[idx] = ai * invS;
    }
}

// ---------------------------------------------------------------------------
extern "C" void kernel_launch(void* const* d_in, const int* in_sizes, int n_in,
                              void* d_out, int out_size) {
    const float* xr = (const float*)d_in[0];
    const float* xi = (const float*)d_in[1];
    float* out = (float*)d_out;

    gram_kernel<<<kB * kSplit, 320>>>(xr, xi);
    combine_kernel<<<kB, 256>>>(out);
}

// round 5
// speedup vs baseline: 1.4219x; 1.4219x over previous
#include <cuda_runtime.h>
#include <cstdint>
#include <cstddef>

// ============================================================================
// ComplexMixture via legacy mma.sync tf32 (compute_103 PTX: no tcgen05/TMA).
// G = X^T X per batch, X = [R | I] (S x 128); symmetric -> 10 upper 32x32
// warp tiles. K split across 8 CTAs/batch (grid 256 = 2 CTAs/SM resident).
// Single-__syncthreads double-buffered pipeline. Deterministic combine.
// ============================================================================

namespace {
constexpr int kB = 32;
constexpr int kS = 8192;
constexpr int kD = 64;
constexpr int kM = 128;                  // 2*D
constexpr int kSplit = 8;
constexpr int kBK = 32;                  // K per pipeline stage
constexpr int kKper = kS / kSplit;       // 1024
constexpr int kIters = kKper / kBK;      // 32
constexpr int kPad = 36;                 // Xt row stride (conflict-free banks)
}  // namespace

// Partial Gram scratch: [B][SPLIT][128][128] f32 = 16 MB (upper tiles valid)
__device__ float g_scratch[(size_t)kB * kSplit * kM * kM];

__device__ __forceinline__ float tf32_rn(float x) {
    uint32_t v;
    asm("cvt.rna.tf32.f32 %0, %1;" : "=r"(v) : "f"(x));
    return __uint_as_float(v);
}

__device__ __forceinline__ void mma_tf32(float* d, const float* a, const float* b) {
    asm volatile(
        "mma.sync.aligned.m16n8k8.row.col.f32.tf32.tf32.f32 "
        "{%0,%1,%2,%3}, {%4,%5,%6,%7}, {%8,%9}, {%0,%1,%2,%3};"
        : "+f"(d[0]), "+f"(d[1]), "+f"(d[2]), "+f"(d[3])
        : "r"(__float_as_uint(a[0])), "r"(__float_as_uint(a[1])),
          "r"(__float_as_uint(a[2])), "r"(__float_as_uint(a[3])),
          "r"(__float_as_uint(b[0])), "r"(__float_as_uint(b[1])));
}

// ---------------------------------------------------------------------------
// Kernel 1: per-(batch, split) partial Gram via mma.sync tf32.
// 320 threads = 10 warps; warp w owns upper 32x32 tile (ti, tj).
// Threads 0..255 are also the loaders. 2 CTAs resident per SM.
// ---------------------------------------------------------------------------
__global__ void __launch_bounds__(320, 2)
gram_kernel(const float* __restrict__ xr, const float* __restrict__ xi) {
    __shared__ float xt[2][kM][kPad];  // 36864 B

    const int t = threadIdx.x;
    const int wid = t >> 5;
    const int lane = t & 31;
    const int b = blockIdx.x >> 3;
    const int p = blockIdx.x & 7;

    // Upper-triangle 32x32 tile assignment for the 10 warps.
    const int ti_tab[10] = {0, 0, 0, 0, 1, 1, 1, 2, 2, 3};
    const int tj_tab[10] = {0, 1, 2, 3, 1, 2, 3, 2, 3, 3};
    const int ti = ti_tab[wid];
    const int tj = tj_tab[wid];

    float acc[2][4][4];
#pragma unroll
    for (int mt = 0; mt < 2; ++mt)
#pragma unroll
        for (int nt = 0; nt < 4; ++nt)
#pragma unroll
            for (int e = 0; e < 4; ++e) acc[mt][nt][e] = 0.0f;

    // Loader mapping: kq = lane&3, mr = lane>>2; k_in = 4*(wid&7)+kq.
    // LDG warp instr: 4 rows x 32B sectors (fully coalesced at sector level).
    // STS bank = (4*mr + k_in) mod 32 over a warp -> all 32 banks, no conflict.
    const int kq = lane & 3;
    const int mr = lane >> 2;
    const int k_in = (wid & 7) * 4 + kq;
    const bool loader = (t < 256);

    const size_t base_off =
        ((size_t)b * kS + (size_t)p * kKper + (size_t)k_in) * kD + (size_t)mr;
    const float* pr = xr + base_off;
    const float* pi = xi + base_off;

    const int fr = lane >> 2;  // fragment row-in-group
    const int fc = lane & 3;   // fragment col-in-group (k)

    float cr[8], ci[8];
    if (loader) {
        // Stage 0 -> smem buf 0 directly; prefetch stage 1 into regs.
#pragma unroll
        for (int j = 0; j < 8; ++j) {
            xt[0][mr + 8 * j][k_in] = tf32_rn(pr[8 * j]);
            xt[0][64 + mr + 8 * j][k_in] = tf32_rn(pi[8 * j]);
        }
#pragma unroll
        for (int j = 0; j < 8; ++j) {
            cr[j] = pr[(size_t)kBK * kD + 8 * j];
            ci[j] = pi[(size_t)kBK * kD + 8 * j];
        }
    }

    for (int it = 0; it < kIters; ++it) {
        const int s = it & 1;
        // One barrier per stage: buf[s] ready (written before previous sync or
        // in prologue), buf[s^1] free (its readers finished before this sync).
        __syncthreads();

        if (loader) {
            if (it + 1 < kIters) {
                // STS stage it+1 from regs into buf[s^1].
#pragma unroll
                for (int j = 0; j < 8; ++j) {
                    xt[s ^ 1][mr + 8 * j][k_in] = tf32_rn(cr[j]);
                    xt[s ^ 1][64 + mr + 8 * j][k_in] = tf32_rn(ci[j]);
                }
            }
            if (it + 2 < kIters) {
                // LDG stage it+2 into regs (covered by the MMA section below).
                const float* prn = pr + (size_t)(it + 2) * kBK * kD;
                const float* pin = pi + (size_t)(it + 2) * kBK * kD;
#pragma unroll
                for (int j = 0; j < 8; ++j) {
                    cr[j] = prn[8 * j];
                    ci[j] = pin[8 * j];
                }
            }
        }

        // MMA over buf[s]: 4 k8 steps.
#pragma unroll
        for (int q = 0; q < 4; ++q) {
            const int kl = q * 8 + fc;
            float a[2][4];
#pragma unroll
            for (int mt = 0; mt < 2; ++mt) {
                const int r0 = ti * 32 + mt * 16;
                a[mt][0] = xt[s][r0 + fr][kl];
                a[mt][1] = xt[s][r0 + fr + 8][kl];
                a[mt][2] = xt[s][r0 + fr][kl + 4];
                a[mt][3] = xt[s][r0 + fr + 8][kl + 4];
            }
            float bf[4][2];
#pragma unroll
            for (int nt = 0; nt < 4; ++nt) {
                const int c0 = tj * 32 + nt * 8;
                bf[nt][0] = xt[s][c0 + fr][kl];
                bf[nt][1] = xt[s][c0 + fr][kl + 4];
            }
#pragma unroll
            for (int mt = 0; mt < 2; ++mt)
#pragma unroll
                for (int nt = 0; nt < 4; ++nt)
                    mma_tf32(acc[mt][nt], a[mt], bf[nt]);
        }
    }

    // Epilogue: write this warp's 32x32 tile to scratch (float2 stores).
    float* scr = g_scratch + (size_t)(b * kSplit + p) * kM * kM;
#pragma unroll
    for (int mt = 0; mt < 2; ++mt) {
#pragma unroll
        for (int nt = 0; nt < 4; ++nt) {
            const int row = ti * 32 + mt * 16 + fr;
            const int col = tj * 32 + nt * 8 + 2 * fc;
            float2 v0 = make_float2(acc[mt][nt][0], acc[mt][nt][1]);
            float2 v1 = make_float2(acc[mt][nt][2], acc[mt][nt][3]);
            *reinterpret_cast<float2*>(scr + (size_t)row * kM + col) = v0;
            *reinterpret_cast<float2*>(scr + (size_t)(row + 8) * kM + col) = v1;
        }
    }
}

// ---------------------------------------------------------------------------
// Kernel 2: deterministic combine of the 8 K-split partials with mirroring
// for skipped lower-triangle tiles. Grid = kB * 8 blocks for full-chip BW.
// out_real[b][i][j] = sum_p (G(i,j) + G(64+i,64+j)) / S
// out_imag[b][i][j] = sum_p (G(i,64+j) - G(j,64+i)) / S
// ---------------------------------------------------------------------------
__global__ void __launch_bounds__(256)
combine_kernel(float* __restrict__ out) {
    const int b = blockIdx.x >> 3;
    const int slice = blockIdx.x & 7;  // 512 outputs per slice
    const float invS = 1.0f / (float)kS;
    float* out_r = out + (size_t)b * kD * kD;
    float* out_i = out + (size_t)kB * kD * kD + (size_t)b * kD * kD;
    const float* base = g_scratch + (size_t)b * kSplit * kM * kM;

    for (int v = 0; v < 2; ++v) {
        const int idx = slice * 512 + v * 256 + threadIdx.x;
        const int i = idx >> 6;
        const int j = idx & 63;
        const bool up = (j >> 5) >= (i >> 5);  // tile (i>>5, j>>5) computed?
        float ar = 0.0f, ai = 0.0f;
#pragma unroll
        for (int pp = 0; pp < kSplit; ++pp) {
            const float* G = base + (size_t)pp * kM * kM;
            ar += up ? (G[i * kM + j] + G[(64 + i) * kM + (64 + j)])
                     : (G[j * kM + i] + G[(64 + j) * kM + (64 + i)]);
            // Block (0,1) tiles are always in the computed upper set.
            ai += G[i * kM + (64 + j)] - G[j * kM + (64 + i)];
        }
        out_r[idx] = ar * invS;
        out_i[idx] = ai * invS;
    }
}

// ---------------------------------------------------------------------------
extern "C" void kernel_launch(void* const* d_in, const int* in_sizes, int n_in,
                              void* d_out, int out_size) {
    const float* xr = (const float*)d_in[0];
    const float* xi = (const float*)d_in[1];
    float* out = (float*)d_out;

    gram_kernel<<<kB * kSplit, 320>>>(xr, xi);
    combine_kernel<<<kB * 8, 256>>>(out);
}

// round 8
// speedup vs baseline: 1.6504x; 1.1607x over previous
#include <cuda_runtime.h>
#include <cstdint>
#include <cstddef>

// ============================================================================
// ComplexMixture via legacy mma.sync tf32 (compute_103 PTX: no tcgen05/TMA).
// G = X^T X per batch, X = [R | I] (S x 128); symmetric -> 10 upper 32x32
// warp tiles. K split across 8 CTAs/batch. ldmatrix operand loads.
// reduce (coalesced) + combine (L2-resident) epilogue kernels.
// ============================================================================

namespace {
constexpr int kB = 32;
constexpr int kS = 8192;
constexpr int kD = 64;
constexpr int kM = 128;                  // 2*D
constexpr int kSplit = 8;
constexpr int kBK = 32;                  // K per pipeline stage
constexpr int kKper = kS / kSplit;       // 1024
constexpr int kIters = kKper / kBK;      // 32
constexpr int kPad = 36;                 // row stride (floats): conflict-free
constexpr int kRowB = kPad * 4;          // 144 bytes
constexpr int kStageBytes = kM * kRowB;  // 18432
}  // namespace

// Partial Gram scratch: [B][SPLIT][128][128] f32 (upper tiles valid)
__device__ float g_scratch[(size_t)kB * kSplit * kM * kM];
// Split-reduced Gram: [B][128][128] f32 (2 MB, L2-resident for combine)
__device__ float g_sum[(size_t)kB * kM * kM];

__device__ __forceinline__ uint32_t smem_u32(const void* p) {
    uint32_t a;
    asm("{ .reg .u64 t; cvta.to.shared.u64 t, %1; cvt.u32.u64 %0, t; }"
        : "=r"(a) : "l"(p));
    return a;
}
__device__ __forceinline__ float tf32_rn(float x) {
    uint32_t v;
    asm("cvt.rna.tf32.f32 %0, %1;" : "=r"(v) : "f"(x));
    return __uint_as_float(v);
}
__device__ __forceinline__ void ldsm_x4(uint32_t addr, uint32_t* r) {
    asm volatile(
        "ldmatrix.sync.aligned.m8n8.x4.shared.b16 {%0,%1,%2,%3}, [%4];"
        : "=r"(r[0]), "=r"(r[1]), "=r"(r[2]), "=r"(r[3]) : "r"(addr));
}
__device__ __forceinline__ void mma_tf32(float* d, const uint32_t* a,
                                         const uint32_t* b) {
    asm volatile(
        "mma.sync.aligned.m16n8k8.row.col.f32.tf32.tf32.f32 "
        "{%0,%1,%2,%3}, {%4,%5,%6,%7}, {%8,%9}, {%0,%1,%2,%3};"
        : "+f"(d[0]), "+f"(d[1]), "+f"(d[2]), "+f"(d[3])
        : "r"(a[0]), "r"(a[1]), "r"(a[2]), "r"(a[3]), "r"(b[0]), "r"(b[1]));
}

// ---------------------------------------------------------------------------
// Kernel 1: per-(batch, split) partial Gram via mma.sync tf32 + ldmatrix.
// 320 threads = 10 warps; warp w owns upper 32x32 tile (ti, tj).
// Threads 0..255 are the loaders. 2 CTAs resident per SM.
// ---------------------------------------------------------------------------
__global__ void __launch_bounds__(320, 2)
gram_kernel(const float* __restrict__ xr, const float* __restrict__ xi) {
    __shared__ float xt[2][kM][kPad];  // 36864 B

    const int t = threadIdx.x;
    const int wid = t >> 5;
    const int lane = t & 31;
    const int b = blockIdx.x >> 3;
    const int p = blockIdx.x & 7;

    const int ti_tab[10] = {0, 0, 0, 0, 1, 1, 1, 2, 2, 3};
    const int tj_tab[10] = {0, 1, 2, 3, 1, 2, 3, 2, 3, 3};
    const int ti = ti_tab[wid];
    const int tj = tj_tab[wid];

    float acc[2][4][4];
#pragma unroll
    for (int mt = 0; mt < 2; ++mt)
#pragma unroll
        for (int nt = 0; nt < 4; ++nt)
#pragma unroll
            for (int e = 0; e < 4; ++e) acc[mt][nt][e] = 0.0f;

    // ldmatrix per-lane smem byte offsets (within a stage buffer).
    // A (mt): rows r0 + (lane&15), k-seg = lane>>4 (16B each).
    // B (ntp): rows c0 + (lane&7) + 8*(lane>>4), k-seg = (lane>>3)&1.
    const uint32_t smem0 = smem_u32(&xt[0][0][0]);
    uint32_t a_off[2], b_off[2];
#pragma unroll
    for (int mt = 0; mt < 2; ++mt)
        a_off[mt] = (uint32_t)((ti * 32 + mt * 16 + (lane & 15)) * kRowB +
                               (lane >> 4) * 16);
#pragma unroll
    for (int ntp = 0; ntp < 2; ++ntp)
        b_off[ntp] = (uint32_t)((tj * 32 + ntp * 16 + (lane & 7) +
                                 ((lane >> 4) * 8)) * kRowB +
                                ((lane >> 3) & 1) * 16);

    // Loader mapping: kq = lane&3, mr = lane>>2; k_in = 4*(wid&7)+kq.
    // LDG warp instr: 4 rows x 32B sectors. STS bank = (4*mr + kq + c) mod 32
    // within a warp -> all 32 banks, conflict-free.
    const int kq = lane & 3;
    const int mr = lane >> 2;
    const int k_in = (wid & 7) * 4 + kq;
    const bool loader = (t < 256);

    const size_t base_off =
        ((size_t)b * kS + (size_t)p * kKper + (size_t)k_in) * kD + (size_t)mr;
    const float* pr = xr + base_off;
    const float* pi = xi + base_off;

    float cr[8], ci[8];
    if (loader) {
#pragma unroll
        for (int j = 0; j < 8; ++j) {
            xt[0][mr + 8 * j][k_in] = tf32_rn(pr[8 * j]);
            xt[0][64 + mr + 8 * j][k_in] = tf32_rn(pi[8 * j]);
        }
#pragma unroll
        for (int j = 0; j < 8; ++j) {
            cr[j] = pr[(size_t)kBK * kD + 8 * j];
            ci[j] = pi[(size_t)kBK * kD + 8 * j];
        }
    }

    for (int it = 0; it < kIters; ++it) {
        const int s = it & 1;
        __syncthreads();  // buf[s] ready; buf[s^1] free

        if (loader) {
            if (it + 1 < kIters) {
#pragma unroll
                for (int j = 0; j < 8; ++j) {
                    xt[s ^ 1][mr + 8 * j][k_in] = tf32_rn(cr[j]);
                    xt[s ^ 1][64 + mr + 8 * j][k_in] = tf32_rn(ci[j]);
                }
            }
            if (it + 2 < kIters) {
                const float* prn = pr + (size_t)(it + 2) * kBK * kD;
                const float* pin = pi + (size_t)(it + 2) * kBK * kD;
#pragma unroll
                for (int j = 0; j < 8; ++j) {
                    cr[j] = prn[8 * j];
                    ci[j] = pin[8 * j];
                }
            }
        }

        const uint32_t sb = smem0 + (uint32_t)(s * kStageBytes);
#pragma unroll
        for (int q = 0; q < 4; ++q) {
            const uint32_t qo = (uint32_t)(q * 32);
            uint32_t A0[4], A1[4], B0[4], B1[4];
            ldsm_x4(sb + a_off[0] + qo, A0);
            ldsm_x4(sb + a_off[1] + qo, A1);
            ldsm_x4(sb + b_off[0] + qo, B0);
            ldsm_x4(sb + b_off[1] + qo, B1);
            mma_tf32(acc[0][0], A0, B0 + 0);
            mma_tf32(acc[0][1], A0, B0 + 2);
            mma_tf32(acc[0][2], A0, B1 + 0);
            mma_tf32(acc[0][3], A0, B1 + 2);
            mma_tf32(acc[1][0], A1, B0 + 0);
            mma_tf32(acc[1][1], A1, B0 + 2);
            mma_tf32(acc[1][2], A1, B1 + 0);
            mma_tf32(acc[1][3], A1, B1 + 2);
        }
    }

    // Epilogue: write this warp's 32x32 tile to scratch (float2 stores).
    const int fr = lane >> 2;
    const int fc = lane & 3;
    float* scr = g_scratch + (size_t)(b * kSplit + p) * kM * kM;
#pragma unroll
    for (int mt = 0; mt < 2; ++mt) {
#pragma unroll
        for (int nt = 0; nt < 4; ++nt) {
            const int row = ti * 32 + mt * 16 + fr;
            const int col = tj * 32 + nt * 8 + 2 * fc;
            float2 v0 = make_float2(acc[mt][nt][0], acc[mt][nt][1]);
            float2 v1 = make_float2(acc[mt][nt][2], acc[mt][nt][3]);
            *reinterpret_cast<float2*>(scr + (size_t)row * kM + col) = v0;
            *reinterpret_cast<float2*>(scr + (size_t)(row + 8) * kM + col) = v1;
        }
    }
}

// ---------------------------------------------------------------------------
// Kernel 2: coalesced split-reduction over the 8 partials (upper tiles only).
// One float4 output per thread; consecutive threads -> consecutive addresses.
// ---------------------------------------------------------------------------
__global__ void __launch_bounds__(256)
reduce_kernel() {
    const int idx = blockIdx.x * 256 + threadIdx.x;  // 0 .. 131071 (float4s)
    const int j4 = idx & 31;
    const int i = (idx >> 5) & 127;
    const int b = idx >> 12;
    if ((j4 >> 3) < (i >> 5)) return;  // lower tile: never written/read

    const size_t pos = (size_t)i * kM + (size_t)(4 * j4);
    const float* base = g_scratch + (size_t)b * kSplit * kM * kM + pos;
    float4 s = make_float4(0.f, 0.f, 0.f, 0.f);
#pragma unroll
    for (int pp = 0; pp < kSplit; ++pp) {
        const float4 v =
            *reinterpret_cast<const float4*>(base + (size_t)pp * kM * kM);
        s.x += v.x; s.y += v.y; s.z += v.z; s.w += v.w;
    }
    *reinterpret_cast<float4*>(g_sum + (size_t)b * kM * kM + pos) = s;
}

// ---------------------------------------------------------------------------
// Kernel 3: combine from the 2 MB g_sum (L2-resident; transposed reads OK).
// out_real[b][i][j] = (G(i,j) + G(64+i,64+j)) / S
// out_imag[b][i][j] = (G(i,64+j) - G(j,64+i)) / S
// ---------------------------------------------------------------------------
__global__ void __launch_bounds__(256)
combine_kernel(float* __restrict__ out) {
    const float invS = 1.0f / (float)kS;
    for (int v = 0; v < 2; ++v) {
        const int idx = blockIdx.x * 512 + v * 256 + threadIdx.x;  // 0..131071
        const int j = idx & 63;
        const int i = (idx >> 6) & 63;
        const int b = idx >> 12;
        const float* G = g_sum + (size_t)b * kM * kM;
        const bool up = (j >> 5) >= (i >> 5);
        const float ar = up ? (G[i * kM + j] + G[(64 + i) * kM + (64 + j)])
                            : (G[j * kM + i] + G[(64 + j) * kM + (64 + i)]);
        const float ai = G[i * kM + (64 + j)] - G[j * kM + (64 + i)];
        out[(size_t)b * kD * kD + (size_t)i * kD + j] = ar * invS;
        out[(size_t)kB * kD * kD + (size_t)b * kD * kD + (size_t)i * kD + j] =
            ai * invS;
    }
}

// ---------------------------------------------------------------------------
extern "C" void kernel_launch(void* const* d_in, const int* in_sizes, int n_in,
                              void* d_out, int out_size) {
    const float* xr = (const float*)d_in[0];
    const float* xi = (const float*)d_in[1];
    float* out = (float*)d_out;

    gram_kernel<<<kB * kSplit, 320>>>(xr, xi);
    reduce_kernel<<<512, 256>>>();
    combine_kernel<<<256, 256>>>(out);
}

// round 12
// speedup vs baseline: 2.5927x; 1.5710x over previous
#include <cuda_runtime.h>
#include <cuda_fp16.h>
#include <cstdint>
#include <cstddef>

// ============================================================================
// ComplexMixture via mma.sync fp16 (same 11-bit significand as tf32).
// G = X^T X per batch, X = [R | I] (S x 128); symmetric -> 10 upper 32x32
// warp tiles. Natural [k][m] fp16 smem layout + ldmatrix.x4.trans for both
// operands (no scalar transpose). K split across 8 CTAs/batch.
// ============================================================================

namespace {
constexpr int kB = 32;
constexpr int kS = 8192;
constexpr int kD = 64;
constexpr int kM = 128;                   // 2*D
constexpr int kSplit = 8;
constexpr int kBK = 32;                   // K rows per stage
constexpr int kKper = kS / kSplit;        // 1024
constexpr int kIters = kKper / kBK;       // 32
constexpr int kRowB = 272;                // bytes/row: 256 data + 16 pad (17x16B)
constexpr int kStageB = kBK * kRowB;      // 8704
}  // namespace

// Partial Gram scratch: [B][SPLIT][128][128] f32 (upper tiles valid)
__device__ float g_scratch[(size_t)kB * kSplit * kM * kM];
// Split-reduced Gram: [B][128][128] f32 (2 MB, L2-resident for combine)
__device__ float g_sum[(size_t)kB * kM * kM];

__device__ __forceinline__ uint32_t smem_u32(const void* p) {
    uint32_t a;
    asm("{ .reg .u64 t; cvta.to.shared.u64 t, %1; cvt.u32.u64 %0, t; }"
        : "=r"(a) : "l"(p));
    return a;
}
__device__ __forceinline__ void ldsm_x4_t(uint32_t addr, uint32_t* r) {
    asm volatile(
        "ldmatrix.sync.aligned.m8n8.x4.trans.shared.b16 {%0,%1,%2,%3}, [%4];"
        : "=r"(r[0]), "=r"(r[1]), "=r"(r[2]), "=r"(r[3]) : "r"(addr));
}
__device__ __forceinline__ void mma_f16(float* d, const uint32_t* a,
                                        const uint32_t* b0, const uint32_t* b1) {
    asm volatile(
        "mma.sync.aligned.m16n8k16.row.col.f32.f16.f16.f32 "
        "{%0,%1,%2,%3}, {%4,%5,%6,%7}, {%8,%9}, {%0,%1,%2,%3};"
        : "+f"(d[0]), "+f"(d[1]), "+f"(d[2]), "+f"(d[3])
        : "r"(a[0]), "r"(a[1]), "r"(a[2]), "r"(a[3]), "r"(*b0), "r"(*b1));
}
__device__ __forceinline__ void sts_f4h(uint32_t addr, float4 v) {
    __half2 lo = __floats2half2_rn(v.x, v.y);
    __half2 hi = __floats2half2_rn(v.z, v.w);
    asm volatile("st.shared.v2.b32 [%0], {%1, %2};"
                 :: "r"(addr),
                    "r"(*reinterpret_cast<uint32_t*>(&lo)),
                    "r"(*reinterpret_cast<uint32_t*>(&hi)) : "memory");
}

// ---------------------------------------------------------------------------
// Kernel 1: per-(batch, split) partial Gram via mma.sync fp16 + ldmatrix.trans
// 320 threads = 10 warps; warp w owns upper 32x32 tile (ti, tj).
// Warps 0..7 are loaders (4 smem rows each per stage). 2 CTAs/SM.
// ---------------------------------------------------------------------------
__global__ void __launch_bounds__(320, 2)
gram_kernel(const float* __restrict__ xr, const float* __restrict__ xi) {
    __shared__ __align__(16) char xt[2 * kStageB];  // 17408 B

    const int t = threadIdx.x;
    const int wid = t >> 5;
    const int lane = t & 31;
    const int b = blockIdx.x >> 3;
    const int p = blockIdx.x & 7;

    const int ti_tab[10] = {0, 0, 0, 0, 1, 1, 1, 2, 2, 3};
    const int tj_tab[10] = {0, 1, 2, 3, 1, 2, 3, 2, 3, 3};
    const int ti = ti_tab[wid];
    const int tj = tj_tab[wid];

    float acc[2][4][4];
#pragma unroll
    for (int mt = 0; mt < 2; ++mt)
#pragma unroll
        for (int nt = 0; nt < 4; ++nt)
#pragma unroll
            for (int e = 0; e < 4; ++e) acc[mt][nt][e] = 0.0f;

    const uint32_t smem0 = smem_u32(xt);

    // ldmatrix.x4.trans lane offsets (bytes within a stage buffer).
    // A x4 at (r0, k0): regs = tiles (mlo,klo),(mhi,klo),(mlo,khi),(mhi,khi)
    //   lane: row = k0 + (l&7) + (g>=2 ? 8:0), colbyte = r0*2 + (g&1 ? 16:0)
    // B x4 at (c0, k0): regs = (nlo,klo),(nlo,khi),(nhi,klo),(nhi,khi)
    //   lane: row = k0 + (l&7) + (g&1 ? 8:0), colbyte = c0*2 + (g>=2 ? 16:0)
    const int g = lane >> 3;
    const int lr = lane & 7;
    uint32_t aoff[2], boff[2];
#pragma unroll
    for (int mt = 0; mt < 2; ++mt) {
        const int r0 = ti * 32 + mt * 16;
        aoff[mt] = (uint32_t)((lr + ((g >= 2) ? 8 : 0)) * kRowB + r0 * 2 +
                              ((g & 1) ? 16 : 0));
    }
#pragma unroll
    for (int np = 0; np < 2; ++np) {
        const int c0 = tj * 32 + np * 16;
        boff[np] = (uint32_t)((lr + ((g & 1) ? 8 : 0)) * kRowB + c0 * 2 +
                              ((g >= 2) ? 16 : 0));
    }

    // Loader mapping: warp w (0..7) owns smem rows w*4 .. w*4+3 per stage.
    // Lanes 0-15: xr (m 0..63), lanes 16-31: xi (m 64..127); float4 each.
    // LDG instr = 2 x 256B contiguous; STS instr = 256B contiguous row.
    const bool loader = (wid < 8);
    const int half_sel = lane >> 4;
    const int li = lane & 15;
    const float* src = half_sel ? xi : xr;
    const size_t gbase =
        ((size_t)b * kS + (size_t)p * kKper + (size_t)(wid * 4)) * kD +
        (size_t)(4 * li);
    const uint32_t sts_off =
        (uint32_t)(wid * 4 * kRowB + half_sel * 128 + li * 8);

    float4 cur[4];
    if (loader) {
        // Stage 0 -> buf 0; prefetch stage 1 into regs.
#pragma unroll
        for (int j = 0; j < 4; ++j) {
            const float4 v =
                *reinterpret_cast<const float4*>(src + gbase + (size_t)j * kD);
            sts_f4h(smem0 + sts_off + (uint32_t)(j * kRowB), v);
        }
#pragma unroll
        for (int j = 0; j < 4; ++j)
            cur[j] = *reinterpret_cast<const float4*>(src + gbase +
                                                      (size_t)(32 + j) * kD);
    }

    for (int it = 0; it < kIters; ++it) {
        const int s = it & 1;
        __syncthreads();  // buf[s] ready; buf[s^1] free

        if (loader) {
            if (it + 1 < kIters) {
                const uint32_t dst = smem0 + (uint32_t)((s ^ 1) * kStageB) + sts_off;
#pragma unroll
                for (int j = 0; j < 4; ++j)
                    sts_f4h(dst + (uint32_t)(j * kRowB), cur[j]);
            }
            if (it + 2 < kIters) {
                const size_t goff = gbase + (size_t)((it + 2) * kBK) * kD;
#pragma unroll
                for (int j = 0; j < 4; ++j)
                    cur[j] = *reinterpret_cast<const float4*>(src + goff +
                                                              (size_t)j * kD);
            }
        }

        const uint32_t sb = smem0 + (uint32_t)(s * kStageB);
#pragma unroll
        for (int ks = 0; ks < 2; ++ks) {
            const uint32_t ko = (uint32_t)(ks * 16 * kRowB);
            uint32_t A0[4], A1[4], B0[4], B1[4];
            ldsm_x4_t(sb + ko + aoff[0], A0);
            ldsm_x4_t(sb + ko + aoff[1], A1);
            ldsm_x4_t(sb + ko + boff[0], B0);
            ldsm_x4_t(sb + ko + boff[1], B1);
            mma_f16(acc[0][0], A0, B0 + 0, B0 + 1);
            mma_f16(acc[0][1], A0, B0 + 2, B0 + 3);
            mma_f16(acc[0][2], A0, B1 + 0, B1 + 1);
            mma_f16(acc[0][3], A0, B1 + 2, B1 + 3);
            mma_f16(acc[1][0], A1, B0 + 0, B0 + 1);
            mma_f16(acc[1][1], A1, B0 + 2, B0 + 3);
            mma_f16(acc[1][2], A1, B1 + 0, B1 + 1);
            mma_f16(acc[1][3], A1, B1 + 2, B1 + 3);
        }
    }

    // Epilogue: write this warp's 32x32 tile to scratch (float2 stores).
    const int fr = lane >> 2;
    const int fc = lane & 3;
    float* scr = g_scratch + (size_t)(b * kSplit + p) * kM * kM;
#pragma unroll
    for (int mt = 0; mt < 2; ++mt) {
#pragma unroll
        for (int nt = 0; nt < 4; ++nt) {
            const int row = ti * 32 + mt * 16 + fr;
            const int col = tj * 32 + nt * 8 + 2 * fc;
            float2 v0 = make_float2(acc[mt][nt][0], acc[mt][nt][1]);
            float2 v1 = make_float2(acc[mt][nt][2], acc[mt][nt][3]);
            *reinterpret_cast<float2*>(scr + (size_t)row * kM + col) = v0;
            *reinterpret_cast<float2*>(scr + (size_t)(row + 8) * kM + col) = v1;
        }
    }
}

// ---------------------------------------------------------------------------
// Kernel 2: coalesced split-reduction over the 8 partials (upper tiles only).
// ---------------------------------------------------------------------------
__global__ void __launch_bounds__(256)
reduce_kernel() {
    const int idx = blockIdx.x * 256 + threadIdx.x;  // 0 .. 131071 (float4s)
    const int j4 = idx & 31;
    const int i = (idx >> 5) & 127;
    const int b = idx >> 12;
    if ((j4 >> 3) < (i >> 5)) return;  // lower tile: never written/read

    const size_t pos = (size_t)i * kM + (size_t)(4 * j4);
    const float* base = g_scratch + (size_t)b * kSplit * kM * kM + pos;
    float4 s = make_float4(0.f, 0.f, 0.f, 0.f);
#pragma unroll
    for (int pp = 0; pp < kSplit; ++pp) {
        const float4 v =
            *reinterpret_cast<const float4*>(base + (size_t)pp * kM * kM);
        s.x += v.x; s.y += v.y; s.z += v.z; s.w += v.w;
    }
    *reinterpret_cast<float4*>(g_sum + (size_t)b * kM * kM + pos) = s;
}

// ---------------------------------------------------------------------------
// Kernel 3: combine from the 2 MB g_sum (L2-resident; transposed reads OK).
// out_real[b][i][j] = (G(i,j) + G(64+i,64+j)) / S
// out_imag[b][i][j] = (G(i,64+j) - G(j,64+i)) / S
// ---------------------------------------------------------------------------
__global__ void __launch_bounds__(256)
combine_kernel(float* __restrict__ out) {
    const float invS = 1.0f / (float)kS;
    for (int v = 0; v < 2; ++v) {
        const int idx = blockIdx.x * 512 + v * 256 + threadIdx.x;  // 0..131071
        const int j = idx & 63;
        const int i = (idx >> 6) & 63;
        const int b = idx >> 12;
        const float* G = g_sum + (size_t)b * kM * kM;
        const bool up = (j >> 5) >= (i >> 5);
        const float ar = up ? (G[i * kM + j] + G[(64 + i) * kM + (64 + j)])
                            : (G[j * kM + i] + G[(64 + j) * kM + (64 + i)]);
        const float ai = G[i * kM + (64 + j)] - G[j * kM + (64 + i)];
        out[(size_t)b * kD * kD + (size_t)i * kD + j] = ar * invS;
        out[(size_t)kB * kD * kD + (size_t)b * kD * kD + (size_t)i * kD + j] =
            ai * invS;
    }
}

// ---------------------------------------------------------------------------
extern "C" void kernel_launch(void* const* d_in, const int* in_sizes, int n_in,
                              void* d_out, int out_size) {
    const float* xr = (const float*)d_in[0];
    const float* xi = (const float*)d_in[1];
    float* out = (float*)d_out;

    gram_kernel<<<kB * kSplit, 320>>>(xr, xi);
    reduce_kernel<<<512, 256>>>();
    combine_kernel<<<256, 256>>>(out);
}